// round 6
// baseline (speedup 1.0000x reference)
#include <cuda_runtime.h>

// CRF NLL mean — B=256, S=512, T=64 (fixed by setup_inputs)
// Inputs (metadata order): emissions f32 (B,S,T), tags int (B,S) [int32 under
//   default JAX x64-disabled; runtime probe handles genuine int64 too],
//   mask i32 (B,S), start_transitions f32 (T), end_transitions f32 (T),
//   transitions f32 (T,T)
// Output: scalar f32 = mean_b( logZ_b - path_score_b )

constexpr int NT = 64;   // tags
constexpr int NB = 256;  // batch
constexpr int NS = 512;  // seq len

__device__ float g_llh[NB];

__global__ __launch_bounds__(NT, 1) void crf_forward_kernel(
    const float* __restrict__ em,          // (B,S,T)
    const int*   __restrict__ tags32,      // (B,S) int32 (or int64 viewed as int32 pairs)
    const int*   __restrict__ mask,        // (B,S)
    const float* __restrict__ startT,      // (T)
    const float* __restrict__ endT,        // (T)
    const float* __restrict__ trans)       // (T,T)
{
    const int b = blockIdx.x;
    const int j = threadIdx.x;   // tag index owned by this thread

    __shared__ __align__(16) float buf[2][NT];
    __shared__ float dterm[NT];
    __shared__ float rsum[NT];
    __shared__ int   rcnt[NT];

    // Runtime tag-dtype probe: if tags are genuinely int64 (nonneg, < 2^31),
    // every odd int32 word is the zero high-word. 16 random tags in [0,64)
    // being all zero has probability 64^-16 — vanishing.
    bool is64 = true;
#pragma unroll
    for (int k = 0; k < 16; k++) is64 &= (tags32[2 * k + 1] == 0);

    // E column j in registers: Ecol[i] = exp(trans[i][j])
    float Ecol[NT];
#pragma unroll
    for (int i = 0; i < NT; i++) Ecol[i] = __expf(trans[i * NT + j]);

    const float* emb  = em + (size_t)b * NS * NT;
    const int*   mrow = mask + b * NS;

    // init: score_j = start_j + em[0][j]  ->  u = exp(score), offset = 0
    float u = __expf(startT[j] + emb[j]);
    int eoff = 0;   // exact log2-domain offset (power-of-two renormalization)

    // prefetch pipeline (depth 4) for emissions + mask
    float ev[4]; int mv[4];
#pragma unroll
    for (int k = 0; k < 4; k++) {
        int s = 1 + k;
        ev[k] = (s < NS) ? emb[s * NT + j] : 0.0f;
        mv[k] = (s < NS) ? mrow[s] : 0;
    }

    for (int s0 = 1; s0 < NS; s0 += 4) {
#pragma unroll
        for (int k = 0; k < 4; k++) {
            int s = s0 + k;
            if (s >= NS) break;                 // uniform across block
            float e_j = __expf(ev[k]);
            int   mk  = mv[k];
            int   sn  = s + 4;
            float ev_n = 0.0f; int mv_n = 0;
            if (sn < NS) { ev_n = emb[sn * NT + j]; mv_n = mrow[sn]; }

            // publish u, one barrier per step (double-buffered)
            buf[s & 1][j] = u;
            __syncthreads();
            const float* pb = buf[s & 1];

            // Common renormalizer: exact power-of-two from tag-0's exponent.
            // Off the critical FFMA path (depends only on pb[0]).
            float u0 = pb[0];
            int   e0 = (__float_as_int(u0) >> 23) - 127;           // floor(log2 u0)
            float sc = __int_as_float((127 - e0) << 23);           // 2^-e0, exact

            float a0=0.f,a1=0.f,a2=0.f,a3=0.f,a4=0.f,a5=0.f,a6=0.f,a7=0.f;
#pragma unroll
            for (int i = 0; i < NT; i += 8) {
                float4 p0 = *(const float4*)(pb + i);
                float4 p1 = *(const float4*)(pb + i + 4);
                a0 = fmaf(p0.x, Ecol[i+0], a0);
                a1 = fmaf(p0.y, Ecol[i+1], a1);
                a2 = fmaf(p0.z, Ecol[i+2], a2);
                a3 = fmaf(p0.w, Ecol[i+3], a3);
                a4 = fmaf(p1.x, Ecol[i+4], a4);
                a5 = fmaf(p1.y, Ecol[i+5], a5);
                a6 = fmaf(p1.z, Ecol[i+6], a6);
                a7 = fmaf(p1.w, Ecol[i+7], a7);
            }
            float acc = ((a0+a1)+(a2+a3)) + ((a4+a5)+(a6+a7));

            if (mk) {
                // u' = (sum_i u_i E_ij) * 2^-e0 * exp(em_j); eoff += e0 (exact)
                u = acc * sc * e_j;
                eoff += e0;
            }
            ev[k] = ev_n; mv[k] = mv_n;
        }
    }

    // ---- denominator terms ----
    dterm[j] = u * __expf(endT[j]);

    // ---- numerator: path score (strided over S) + mask count ----
    float part = 0.0f; int mcount = 0;
    const size_t tbase = (size_t)b * NS;
    for (int s = j; s < NS; s += NT) {
        size_t idx  = tbase + s;
        int t = is64 ? tags32[2 * idx] : tags32[idx];
        float emv = emb[s * NT + t];
        if (s == 0) {
            part += startT[t] + emv;
        } else if (mrow[s]) {
            size_t idp = tbase + s - 1;
            int tp = is64 ? tags32[2 * idp] : tags32[idp];
            part += trans[tp * NT + t] + emv;
        }
        mcount += (mrow[s] != 0);
    }
    rsum[j] = part; rcnt[j] = mcount;
    __syncthreads();

    if (j == 0) {
        float ds = 0.0f, ns = 0.0f; int mc = 0;
#pragma unroll
        for (int i = 0; i < NT; i++) { ds += dterm[i]; ns += rsum[i]; mc += rcnt[i]; }
        size_t lidx = tbase + (mc - 1);
        int last = is64 ? tags32[2 * lidx] : tags32[lidx];
        ns += endT[last];
        double denom = (double)eoff * 0.6931471805599453 + (double)logf(ds);
        g_llh[b] = (float)(denom - (double)ns);
    }
}

__global__ void crf_reduce_kernel(float* __restrict__ out)
{
    __shared__ float sh[NB];
    int t = threadIdx.x;
    sh[t] = g_llh[t];
    __syncthreads();
    for (int stride = NB / 2; stride > 0; stride >>= 1) {
        if (t < stride) sh[t] += sh[t + stride];
        __syncthreads();
    }
    if (t == 0) out[0] = sh[0] / (float)NB;
}

extern "C" void kernel_launch(void* const* d_in, const int* in_sizes, int n_in,
                              void* d_out, int out_size)
{
    const float* em   = (const float*)d_in[0];
    const int*   tags = (const int*)d_in[1];
    const int*   mask = (const int*)d_in[2];
    const float* st   = (const float*)d_in[3];
    const float* en   = (const float*)d_in[4];
    const float* tr   = (const float*)d_in[5];

    crf_forward_kernel<<<NB, NT>>>(em, tags, mask, st, en, tr);
    crf_reduce_kernel<<<1, NB>>>((float*)d_out);
}